// round 5
// baseline (speedup 1.0000x reference)
#include <cuda_runtime.h>
#include <cuda_fp16.h>

#define NMAX 50000
#define EMAX 800000
#define GMAX 2500
#define ETOT (EMAX + NMAX)

// packed dual-fp32 helpers (sm_100+ PTX)
#define PACK2(out, f) asm("mov.b64 %0, {%1, %1};" : "=l"(out) : "r"(__float_as_uint(f)))
#define FMA2(d, a, b) asm("fma.rn.f32x2 %0, %1, %2, %0;" : "+l"(d) : "l"(a), "l"(b))
#define UNPACK2(lo, hi, v) asm("mov.b64 {%0, %1}, %2;" : "=r"(lo), "=r"(hi) : "l"(v))

// ---------------- scratch (device globals; no allocation allowed) ----------------
__device__ uint2 g_h16[NMAX * 32];     // per-layer hidden, fp16: [N][32 lanes x 4 half]
__device__ float g_f0[NMAX * 64];      // layer output ping (fp32)
__device__ float g_f1[NMAX * 64];      // layer output pong
__device__ float g_att[NMAX * 4];      // per node: a_src0, a_src1, a_dst0, a_dst1
__device__ int   g_rp[NMAX + 1];       // CSR row_ptr by dst
__device__ int   g_deg[NMAX];
__device__ int   g_fill[NMAX];
__device__ int   g_csrc[ETOT];         // CSR src indices
__device__ float g_gsum[GMAX];
__device__ float g_gcnt[GMAX];

// ---------------- CSR build (dst is layer-invariant) + pool zero/count -----------
__global__ void k_init(int n, int g) {
  int i = blockIdx.x * blockDim.x + threadIdx.x;
  if (i < n) { g_deg[i] = 1; g_fill[i] = 0; }   // 1 = self loop
  if (i < g) { g_gsum[i] = 0.f; g_gcnt[i] = 0.f; }
}

// 4 edges per thread -> 4 independent atomics in flight
__global__ void k_count(const int* __restrict__ ei, int E) {
  int i = blockIdx.x * blockDim.x + threadIdx.x;
  int E4 = E >> 2;
  if (i < E4) {
    int4 d = ((const int4*)(ei + E))[i];
    atomicAdd(&g_deg[d.x], 1);
    atomicAdd(&g_deg[d.y], 1);
    atomicAdd(&g_deg[d.z], 1);
    atomicAdd(&g_deg[d.w], 1);
  } else {
    int j = (E4 << 2) + (i - E4);
    if (j < E) atomicAdd(&g_deg[ei[E + j]], 1);
  }
}

// graph-size counts for mean pooling (independent of everything but batch)
__global__ void k_cnt_batch(const int* __restrict__ batch, int n) {
  int i = blockIdx.x * blockDim.x + threadIdx.x;
  if (i < n) atomicAdd(&g_gcnt[batch[i]], 1.f);
}

__global__ void k_scan(int n) {
  __shared__ int sums[1024];
  int t = threadIdx.x;
  int chunk = (n + 1023) / 1024;
  int b = t * chunk;
  int e = min(b + chunk, n);
  int s = 0;
  for (int i = b; i < e; i++) s += g_deg[i];
  sums[t] = s;
  __syncthreads();
  for (int o = 1; o < 1024; o <<= 1) {
    int v = (t >= o) ? sums[t - o] : 0;
    __syncthreads();
    sums[t] += v;
    __syncthreads();
  }
  int run = sums[t] - s;   // exclusive prefix
  for (int i = b; i < e; i++) { g_rp[i] = run; run += g_deg[i]; }
  if (t == 1023) g_rp[n] = sums[1023];
}

// 4 edges per thread; self-loops appended in the same grid
__global__ void k_scatter(const int* __restrict__ ei, int E, int n) {
  int i = blockIdx.x * blockDim.x + threadIdx.x;
  int E4 = E >> 2;
  if (i < E4) {
    int4 s = ((const int4*)ei)[i];
    int4 d = ((const int4*)(ei + E))[i];
    int px = atomicAdd(&g_fill[d.x], 1);
    int py = atomicAdd(&g_fill[d.y], 1);
    int pz = atomicAdd(&g_fill[d.z], 1);
    int pw = atomicAdd(&g_fill[d.w], 1);
    g_csrc[g_rp[d.x] + px] = s.x;
    g_csrc[g_rp[d.y] + py] = s.y;
    g_csrc[g_rp[d.z] + pz] = s.z;
    g_csrc[g_rp[d.w] + pw] = s.w;
  } else {
    int tail = E - (E4 << 2);
    int j = i - E4;
    if (j < tail) {
      int jj = (E4 << 2) + j;
      int s = ei[jj], d = ei[E + jj];
      int pos = atomicAdd(&g_fill[d], 1);
      g_csrc[g_rp[d] + pos] = s;
    } else {
      int v = j - tail;
      if (v < n) {
        int pos = atomicAdd(&g_fill[v], 1);
        g_csrc[g_rp[v] + pos] = v;   // self loop
      }
    }
  }
}

// ---------------- GEMM + fused attention dots -----------------------------------
// h[N,128] = X[N,fin] @ W[fin,128]; attention dots from live fp32 accumulators;
// h stored fp16 (message payload only). block = 128 thr, 32-row tile, f32x2 FMAs.
__global__ void k_gemm(const float* __restrict__ Xin, int insel,
                       const float* __restrict__ W,
                       const float* __restrict__ asrc,
                       const float* __restrict__ adst, int n, int fin) {
  const float* X = Xin ? Xin : (insel ? g_f1 : g_f0);
  __shared__ float xs[32 * 128];
  int tid = threadIdx.x;
  int lane = tid & 31;
  int row0 = blockIdx.x * 32;
  int fin4 = fin >> 2;
  int nf4 = 32 * fin4;
  const float4* X4 = (const float4*)X;
  for (int i = tid; i < nf4; i += 128) {
    int row = i / fin4;
    int kk = i - row * fin4;
    float4 v = make_float4(0.f, 0.f, 0.f, 0.f);
    if (row0 + row < n) v = X4[(row0 + row) * fin4 + kk];
    ((float4*)xs)[i] = v;
  }
  __syncthreads();
  int colg = lane;
  int rowseg = tid >> 5;
  unsigned long long acc[8][2];
#pragma unroll
  for (int r = 0; r < 8; r++) { acc[r][0] = 0ULL; acc[r][1] = 0ULL; }
  const float* xb = &xs[(rowseg * 8) * fin];
  const float* wb = &W[colg * 4];
  for (int k = 0; k < fin; k += 4) {
    ulonglong2 w0 = *(const ulonglong2*)&wb[(k + 0) * 128];
    ulonglong2 w1 = *(const ulonglong2*)&wb[(k + 1) * 128];
    ulonglong2 w2 = *(const ulonglong2*)&wb[(k + 2) * 128];
    ulonglong2 w3 = *(const ulonglong2*)&wb[(k + 3) * 128];
#pragma unroll
    for (int r = 0; r < 8; r++) {
      float4 x4 = *(const float4*)&xb[r * fin + k];
      unsigned long long xx;
      PACK2(xx, x4.x); FMA2(acc[r][0], xx, w0.x); FMA2(acc[r][1], xx, w0.y);
      PACK2(xx, x4.y); FMA2(acc[r][0], xx, w1.x); FMA2(acc[r][1], xx, w1.y);
      PACK2(xx, x4.z); FMA2(acc[r][0], xx, w2.x); FMA2(acc[r][1], xx, w2.y);
      PACK2(xx, x4.w); FMA2(acc[r][0], xx, w3.x); FMA2(acc[r][1], xx, w3.y);
    }
  }
  // epilogue: attention dots (fp32 exact) + fp16 h store
  float4 as4 = *(const float4*)&asrc[colg * 4];   // att layout [H*C]=[128] matches cols
  float4 ad4 = *(const float4*)&adst[colg * 4];
#pragma unroll
  for (int r = 0; r < 8; r++) {
    int row = row0 + rowseg * 8 + r;
    unsigned a, b, c, d;
    UNPACK2(a, b, acc[r][0]);
    UNPACK2(c, d, acc[r][1]);
    float4 hv = make_float4(__uint_as_float(a), __uint_as_float(b),
                            __uint_as_float(c), __uint_as_float(d));
    float ss = hv.x * as4.x + hv.y * as4.y + hv.z * as4.z + hv.w * as4.w;
    float sd = hv.x * ad4.x + hv.y * ad4.y + hv.z * ad4.z + hv.w * ad4.w;
#pragma unroll
    for (int o = 8; o; o >>= 1) {   // reduce within each 16-lane head half
      ss += __shfl_xor_sync(0xffffffffu, ss, o);
      sd += __shfl_xor_sync(0xffffffffu, sd, o);
    }
    float ss1 = __shfl_sync(0xffffffffu, ss, 16);
    float sd1 = __shfl_sync(0xffffffffu, sd, 16);
    if (row < n) {
      half2 p0 = __floats2half2_rn(hv.x, hv.y);
      half2 p1 = __floats2half2_rn(hv.z, hv.w);
      uint2 hp;
      hp.x = *(unsigned*)&p0;
      hp.y = *(unsigned*)&p1;
      g_h16[row * 32 + colg] = hp;
      if (lane == 0) *(float4*)&g_att[4 * row] = make_float4(ss, ss1, sd, sd1);
    }
  }
}

// ---------------- softmax + aggregate + head-mean + bias + relu ------------------
// one warp per destination node, phase-split (see round 4).
__global__ void k_agg(const float* __restrict__ bias, int outsel, int n) {
  float* OUT = outsel ? g_f1 : g_f0;
  int v = blockIdx.x * 8 + (threadIdx.x >> 5);
  int lane = threadIdx.x & 31;
  if (v >= n) return;
  int rs = g_rp[v], re = g_rp[v + 1];
  float2 adv = *(const float2*)&g_att[4 * v + 2];
  bool head1 = lane >= 16;

  float s0 = 0.f, s1 = 0.f;
  float4 acc = make_float4(0.f, 0.f, 0.f, 0.f);
  for (int base = rs; base < re; base += 32) {
    int jj = base + lane;
    int s_l = 0;
    float x0 = 0.f, x1 = 0.f;
    if (jj < re) {
      s_l = g_csrc[jj];                                 // coalesced
      float2 as = *(const float2*)&g_att[4 * s_l];      // independent gathers
      float e0 = as.x + adv.x; e0 = fmaxf(e0, 0.2f * e0);
      float e1 = as.y + adv.y; e1 = fmaxf(e1, 0.2f * e1);
      x0 = __expf(e0); x1 = __expf(e1);
    }
    s0 += x0; s1 += x1;
    int cnt = min(re - base, 32);
#pragma unroll 4
    for (int k = 0; k < cnt; k++) {
      int s = __shfl_sync(0xffffffffu, s_l, k);
      float xa = __shfl_sync(0xffffffffu, x0, k);
      float xb = __shfl_sync(0xffffffffu, x1, k);
      float xw = head1 ? xb : xa;
      uint2 hp = g_h16[s * 32 + lane];                  // independent 256B/warp
      float2 f0 = __half22float2(*(half2*)&hp.x);
      float2 f1 = __half22float2(*(half2*)&hp.y);
      acc.x += xw * f0.x; acc.y += xw * f0.y;
      acc.z += xw * f1.x; acc.w += xw * f1.y;
    }
  }
#pragma unroll
  for (int o = 16; o; o >>= 1) {
    s0 += __shfl_xor_sync(0xffffffffu, s0, o);
    s1 += __shfl_xor_sync(0xffffffffu, s1, o);
  }
  float r0 = 0.5f / fmaxf(s0, 1e-16f);
  float r1 = 0.5f / fmaxf(s1, 1e-16f);
  float rw = head1 ? r1 : r0;
  acc.x *= rw; acc.y *= rw; acc.z *= rw; acc.w *= rw;
  float px = __shfl_xor_sync(0xffffffffu, acc.x, 16);
  float py = __shfl_xor_sync(0xffffffffu, acc.y, 16);
  float pz = __shfl_xor_sync(0xffffffffu, acc.z, 16);
  float pw = __shfl_xor_sync(0xffffffffu, acc.w, 16);
  if (!head1) {
    float4 b4 = *(const float4*)&bias[lane * 4];
    float4 o;
    o.x = fmaxf(acc.x + px + b4.x, 0.f);
    o.y = fmaxf(acc.y + py + b4.y, 0.f);
    o.z = fmaxf(acc.z + pz + b4.z, 0.f);
    o.w = fmaxf(acc.w + pw + b4.w, 0.f);
    *(float4*)&OUT[v * 64 + lane * 4] = o;
  }
}

// ---------------- pooling + final linear -----------------------------------------
__global__ void k_pool(const float* __restrict__ lw, const int* __restrict__ batch, int n) {
  int v = blockIdx.x * 8 + (threadIdx.x >> 5);
  int lane = threadIdx.x & 31;
  if (v >= n) return;
  const float* fp = &g_f0[v * 64];
  float p = fp[lane] * lw[lane] + fp[lane + 32] * lw[lane + 32];
#pragma unroll
  for (int o = 16; o; o >>= 1) p += __shfl_xor_sync(0xffffffffu, p, o);
  if (lane == 0) atomicAdd(&g_gsum[batch[v]], p);
}

__global__ void k_final(const float* __restrict__ lb, float* __restrict__ out, int g) {
  int i = blockIdx.x * blockDim.x + threadIdx.x;
  if (i < g) out[i] = g_gsum[i] / fmaxf(g_gcnt[i], 1.f) + lb[0];
}

// ---------------- launch ----------------------------------------------------------
extern "C" void kernel_launch(void* const* d_in, const int* in_sizes, int n_in,
                              void* d_out, int out_size) {
  int base;
  const int *ei, *bat;
  int Esz;
  if (in_sizes[1] > 1000000) {          // dict order: x, edge_index, batch, ...
    ei = (const int*)d_in[1];
    bat = (const int*)d_in[2];
    base = 3;
    Esz = in_sizes[1];
  } else {                               // signature order
    base = 1;
    ei = (const int*)d_in[15];
    bat = (const int*)d_in[16];
    Esz = in_sizes[15];
  }
  const float* x   = (const float*)d_in[0];
  const float* W1  = (const float*)d_in[base + 0];
  const float* as1 = (const float*)d_in[base + 1];
  const float* ad1 = (const float*)d_in[base + 2];
  const float* b1  = (const float*)d_in[base + 3];
  const float* W2  = (const float*)d_in[base + 4];
  const float* as2 = (const float*)d_in[base + 5];
  const float* ad2 = (const float*)d_in[base + 6];
  const float* b2  = (const float*)d_in[base + 7];
  const float* W3  = (const float*)d_in[base + 8];
  const float* as3 = (const float*)d_in[base + 9];
  const float* ad3 = (const float*)d_in[base + 10];
  const float* b3  = (const float*)d_in[base + 11];
  const float* lw  = (const float*)d_in[base + 12];
  const float* lb  = (const float*)d_in[base + 13];

  int n = in_sizes[0] / 128;
  int E = Esz / 2;
  int G = out_size;

  // side stream + fork/join events: created lazily on the FIRST call (the
  // uncaptured correctness run), reused on every subsequent call, so the
  // captured work graph is identical call-to-call.
  static cudaStream_t s_side = nullptr;
  static cudaEvent_t ev_fork = nullptr, ev_join = nullptr;
  if (!s_side) {
    cudaStreamCreateWithFlags(&s_side, cudaStreamNonBlocking);
    cudaEventCreateWithFlags(&ev_fork, cudaEventDisableTiming);
    cudaEventCreateWithFlags(&ev_join, cudaEventDisableTiming);
  }

  const int tb = 256;
  int gb = (n + 31) / 32;
  int wg = (n + 7) / 8;
  int E4 = E >> 2;
  int tailE = E - (E4 << 2);

  // fork: CSR build + pool counts on side stream, GEMM layer 1 on main stream
  cudaEventRecord(ev_fork, 0);
  cudaStreamWaitEvent(s_side, ev_fork, 0);
  k_init<<<(n + tb - 1) / tb, tb, 0, s_side>>>(n, G);
  k_count<<<(E4 + tailE + tb - 1) / tb, tb, 0, s_side>>>(ei, E);
  k_cnt_batch<<<(n + tb - 1) / tb, tb, 0, s_side>>>(bat, n);
  k_scan<<<1, 1024, 0, s_side>>>(n);
  k_scatter<<<(E4 + tailE + n + tb - 1) / tb, tb, 0, s_side>>>(ei, E, n);
  cudaEventRecord(ev_join, s_side);

  k_gemm<<<gb, 128>>>(x, 0, W1, as1, ad1, n, 128);

  // join: aggregation needs both h/att (main) and CSR (side)
  cudaStreamWaitEvent(0, ev_join, 0);
  k_agg<<<wg, 256>>>(b1, 0, n);
  k_gemm<<<gb, 128>>>(nullptr, 0, W2, as2, ad2, n, 64);
  k_agg<<<wg, 256>>>(b2, 1, n);
  k_gemm<<<gb, 128>>>(nullptr, 1, W3, as3, ad3, n, 64);
  k_agg<<<wg, 256>>>(b3, 0, n);

  k_pool<<<wg, 256>>>(lw, bat, n);
  k_final<<<(G + tb - 1) / tb, tb>>>(lb, (float*)d_out, G);
}

// round 6
// speedup vs baseline: 1.1993x; 1.1993x over previous
#include <cuda_runtime.h>
#include <cuda_fp16.h>

#define NMAX 50000
#define EMAX 800000
#define GMAX 2500
#define ETOT (EMAX + NMAX)
#define SCAN_B 512
#define SCAN_NB ((NMAX + SCAN_B - 1) / SCAN_B)   // 98

// packed dual-fp32 helpers (sm_100+ PTX)
#define PACK2(out, f) asm("mov.b64 %0, {%1, %1};" : "=l"(out) : "r"(__float_as_uint(f)))
#define FMA2(d, a, b) asm("fma.rn.f32x2 %0, %1, %2, %0;" : "+l"(d) : "l"(a), "l"(b))
#define UNPACK2(lo, hi, v) asm("mov.b64 {%0, %1}, %2;" : "=r"(lo), "=r"(hi) : "l"(v))

// ---------------- scratch (device globals; no allocation allowed) ----------------
__device__ uint2 g_h16[NMAX * 32];     // per-layer hidden, fp16: [N][32 lanes x 4 half]
__device__ float g_f0[NMAX * 64];      // layer output ping (fp32)
__device__ float g_f1[NMAX * 64];      // layer output pong
__device__ float g_att[NMAX * 4];      // per node: a_src0, a_src1, a_dst0, a_dst1
__device__ int   g_rp[NMAX + 1];       // CSR row_ptr by dst
__device__ int   g_deg[NMAX];
__device__ int   g_fill[NMAX];
__device__ int   g_csrc[ETOT];         // CSR src indices
__device__ float g_gsum[GMAX];
__device__ float g_gcnt[GMAX];
__device__ int   g_bsum[SCAN_NB + 1];
__device__ int   g_boff[SCAN_NB + 1];

// ---------------- CSR build (dst is layer-invariant) + pool zero/count -----------
__global__ void k_init(int n, int g) {
  int i = blockIdx.x * blockDim.x + threadIdx.x;
  if (i < n) { g_deg[i] = 1; g_fill[i] = 0; }   // 1 = self loop
  if (i < g) { g_gsum[i] = 0.f; g_gcnt[i] = 0.f; }
}

// 4 edges per thread -> 4 independent atomics in flight
__global__ void k_count(const int* __restrict__ ei, int E) {
  int i = blockIdx.x * blockDim.x + threadIdx.x;
  int E4 = E >> 2;
  if (i < E4) {
    int4 d = ((const int4*)(ei + E))[i];
    atomicAdd(&g_deg[d.x], 1);
    atomicAdd(&g_deg[d.y], 1);
    atomicAdd(&g_deg[d.z], 1);
    atomicAdd(&g_deg[d.w], 1);
  } else {
    int j = (E4 << 2) + (i - E4);
    if (j < E) atomicAdd(&g_deg[ei[E + j]], 1);
  }
}

// graph-size counts for mean pooling (depends only on batch)
__global__ void k_cnt_batch(const int* __restrict__ batch, int n) {
  int i = blockIdx.x * blockDim.x + threadIdx.x;
  if (i < n) atomicAdd(&g_gcnt[batch[i]], 1.f);
}

// ---------- parallel 3-phase exclusive scan of g_deg -> g_rp ----------
__global__ void k_scan1(int n) {
  __shared__ int sh[SCAN_B];
  int t = threadIdx.x;
  int i = blockIdx.x * SCAN_B + t;
  int v = (i < n) ? g_deg[i] : 0;
  sh[t] = v;
  __syncthreads();
#pragma unroll
  for (int o = 1; o < SCAN_B; o <<= 1) {
    int x = (t >= o) ? sh[t - o] : 0;
    __syncthreads();
    sh[t] += x;
    __syncthreads();
  }
  if (i < n) g_rp[i] = sh[t] - v;            // exclusive, pre-offset
  if (t == SCAN_B - 1) g_bsum[blockIdx.x] = sh[t];
}

__global__ void k_scan2(int nb, int n) {
  __shared__ int sh[128];
  int t = threadIdx.x;
  int v = (t < nb) ? g_bsum[t] : 0;
  sh[t] = v;
  __syncthreads();
#pragma unroll
  for (int o = 1; o < 128; o <<= 1) {
    int x = (t >= o) ? sh[t - o] : 0;
    __syncthreads();
    sh[t] += x;
    __syncthreads();
  }
  if (t < nb) g_boff[t] = sh[t] - v;          // exclusive block offsets
  if (t == 127) g_rp[n] = sh[127];            // grand total
}

__global__ void k_scan3(int n) {
  int i = blockIdx.x * SCAN_B + threadIdx.x;
  if (i < n) g_rp[i] += g_boff[blockIdx.x];
}

// 4 edges per thread; self-loops appended in the same grid
__global__ void k_scatter(const int* __restrict__ ei, int E, int n) {
  int i = blockIdx.x * blockDim.x + threadIdx.x;
  int E4 = E >> 2;
  if (i < E4) {
    int4 s = ((const int4*)ei)[i];
    int4 d = ((const int4*)(ei + E))[i];
    int px = atomicAdd(&g_fill[d.x], 1);
    int py = atomicAdd(&g_fill[d.y], 1);
    int pz = atomicAdd(&g_fill[d.z], 1);
    int pw = atomicAdd(&g_fill[d.w], 1);
    g_csrc[g_rp[d.x] + px] = s.x;
    g_csrc[g_rp[d.y] + py] = s.y;
    g_csrc[g_rp[d.z] + pz] = s.z;
    g_csrc[g_rp[d.w] + pw] = s.w;
  } else {
    int tail = E - (E4 << 2);
    int j = i - E4;
    if (j < tail) {
      int jj = (E4 << 2) + j;
      int s = ei[jj], d = ei[E + jj];
      int pos = atomicAdd(&g_fill[d], 1);
      g_csrc[g_rp[d] + pos] = s;
    } else {
      int v = j - tail;
      if (v < n) {
        int pos = atomicAdd(&g_fill[v], 1);
        g_csrc[g_rp[v] + pos] = v;   // self loop
      }
    }
  }
}

// ---------------- GEMM + fused attention dots -----------------------------------
__global__ void k_gemm(const float* __restrict__ Xin, int insel,
                       const float* __restrict__ W,
                       const float* __restrict__ asrc,
                       const float* __restrict__ adst, int n, int fin) {
  const float* X = Xin ? Xin : (insel ? g_f1 : g_f0);
  __shared__ float xs[32 * 128];
  int tid = threadIdx.x;
  int lane = tid & 31;
  int row0 = blockIdx.x * 32;
  int fin4 = fin >> 2;
  int nf4 = 32 * fin4;
  const float4* X4 = (const float4*)X;
  for (int i = tid; i < nf4; i += 128) {
    int row = i / fin4;
    int kk = i - row * fin4;
    float4 v = make_float4(0.f, 0.f, 0.f, 0.f);
    if (row0 + row < n) v = X4[(row0 + row) * fin4 + kk];
    ((float4*)xs)[i] = v;
  }
  __syncthreads();
  int colg = lane;
  int rowseg = tid >> 5;
  unsigned long long acc[8][2];
#pragma unroll
  for (int r = 0; r < 8; r++) { acc[r][0] = 0ULL; acc[r][1] = 0ULL; }
  const float* xb = &xs[(rowseg * 8) * fin];
  const float* wb = &W[colg * 4];
  for (int k = 0; k < fin; k += 4) {
    ulonglong2 w0 = *(const ulonglong2*)&wb[(k + 0) * 128];
    ulonglong2 w1 = *(const ulonglong2*)&wb[(k + 1) * 128];
    ulonglong2 w2 = *(const ulonglong2*)&wb[(k + 2) * 128];
    ulonglong2 w3 = *(const ulonglong2*)&wb[(k + 3) * 128];
#pragma unroll
    for (int r = 0; r < 8; r++) {
      float4 x4 = *(const float4*)&xb[r * fin + k];
      unsigned long long xx;
      PACK2(xx, x4.x); FMA2(acc[r][0], xx, w0.x); FMA2(acc[r][1], xx, w0.y);
      PACK2(xx, x4.y); FMA2(acc[r][0], xx, w1.x); FMA2(acc[r][1], xx, w1.y);
      PACK2(xx, x4.z); FMA2(acc[r][0], xx, w2.x); FMA2(acc[r][1], xx, w2.y);
      PACK2(xx, x4.w); FMA2(acc[r][0], xx, w3.x); FMA2(acc[r][1], xx, w3.y);
    }
  }
  // epilogue: attention dots (fp32 exact) + fp16 h store
  float4 as4 = *(const float4*)&asrc[colg * 4];
  float4 ad4 = *(const float4*)&adst[colg * 4];
#pragma unroll
  for (int r = 0; r < 8; r++) {
    int row = row0 + rowseg * 8 + r;
    unsigned a, b, c, d;
    UNPACK2(a, b, acc[r][0]);
    UNPACK2(c, d, acc[r][1]);
    float4 hv = make_float4(__uint_as_float(a), __uint_as_float(b),
                            __uint_as_float(c), __uint_as_float(d));
    float ss = hv.x * as4.x + hv.y * as4.y + hv.z * as4.z + hv.w * as4.w;
    float sd = hv.x * ad4.x + hv.y * ad4.y + hv.z * ad4.z + hv.w * ad4.w;
#pragma unroll
    for (int o = 8; o; o >>= 1) {
      ss += __shfl_xor_sync(0xffffffffu, ss, o);
      sd += __shfl_xor_sync(0xffffffffu, sd, o);
    }
    float ss1 = __shfl_sync(0xffffffffu, ss, 16);
    float sd1 = __shfl_sync(0xffffffffu, sd, 16);
    if (row < n) {
      half2 p0 = __floats2half2_rn(hv.x, hv.y);
      half2 p1 = __floats2half2_rn(hv.z, hv.w);
      uint2 hp;
      hp.x = *(unsigned*)&p0;
      hp.y = *(unsigned*)&p1;
      g_h16[row * 32 + colg] = hp;
      if (lane == 0) *(float4*)&g_att[4 * row] = make_float4(ss, ss1, sd, sd1);
    }
  }
}

// ---------------- softmax + aggregate + head-mean + bias + relu ------------------
__global__ void k_agg(const float* __restrict__ bias, int outsel, int n) {
  float* OUT = outsel ? g_f1 : g_f0;
  int v = blockIdx.x * 8 + (threadIdx.x >> 5);
  int lane = threadIdx.x & 31;
  if (v >= n) return;
  int rs = g_rp[v], re = g_rp[v + 1];
  float2 adv = *(const float2*)&g_att[4 * v + 2];
  bool head1 = lane >= 16;

  float s0 = 0.f, s1 = 0.f;
  float4 acc = make_float4(0.f, 0.f, 0.f, 0.f);
  for (int base = rs; base < re; base += 32) {
    int jj = base + lane;
    int s_l = 0;
    float x0 = 0.f, x1 = 0.f;
    if (jj < re) {
      s_l = g_csrc[jj];                                 // coalesced
      float2 as = *(const float2*)&g_att[4 * s_l];      // independent gathers
      float e0 = as.x + adv.x; e0 = fmaxf(e0, 0.2f * e0);
      float e1 = as.y + adv.y; e1 = fmaxf(e1, 0.2f * e1);
      x0 = __expf(e0); x1 = __expf(e1);
    }
    s0 += x0; s1 += x1;
    int cnt = min(re - base, 32);
#pragma unroll 4
    for (int k = 0; k < cnt; k++) {
      int s = __shfl_sync(0xffffffffu, s_l, k);
      float xa = __shfl_sync(0xffffffffu, x0, k);
      float xb = __shfl_sync(0xffffffffu, x1, k);
      float xw = head1 ? xb : xa;
      uint2 hp = g_h16[s * 32 + lane];                  // independent 256B/warp
      float2 f0 = __half22float2(*(half2*)&hp.x);
      float2 f1 = __half22float2(*(half2*)&hp.y);
      acc.x += xw * f0.x; acc.y += xw * f0.y;
      acc.z += xw * f1.x; acc.w += xw * f1.y;
    }
  }
#pragma unroll
  for (int o = 16; o; o >>= 1) {
    s0 += __shfl_xor_sync(0xffffffffu, s0, o);
    s1 += __shfl_xor_sync(0xffffffffu, s1, o);
  }
  float r0 = 0.5f / fmaxf(s0, 1e-16f);
  float r1 = 0.5f / fmaxf(s1, 1e-16f);
  float rw = head1 ? r1 : r0;
  acc.x *= rw; acc.y *= rw; acc.z *= rw; acc.w *= rw;
  float px = __shfl_xor_sync(0xffffffffu, acc.x, 16);
  float py = __shfl_xor_sync(0xffffffffu, acc.y, 16);
  float pz = __shfl_xor_sync(0xffffffffu, acc.z, 16);
  float pw = __shfl_xor_sync(0xffffffffu, acc.w, 16);
  if (!head1) {
    float4 b4 = *(const float4*)&bias[lane * 4];
    float4 o;
    o.x = fmaxf(acc.x + px + b4.x, 0.f);
    o.y = fmaxf(acc.y + py + b4.y, 0.f);
    o.z = fmaxf(acc.z + pz + b4.z, 0.f);
    o.w = fmaxf(acc.w + pw + b4.w, 0.f);
    *(float4*)&OUT[v * 64 + lane * 4] = o;
  }
}

// ---------------- pooling + final linear -----------------------------------------
__global__ void k_pool(const float* __restrict__ lw, const int* __restrict__ batch, int n) {
  int v = blockIdx.x * 8 + (threadIdx.x >> 5);
  int lane = threadIdx.x & 31;
  if (v >= n) return;
  const float* fp = &g_f0[v * 64];
  float p = fp[lane] * lw[lane] + fp[lane + 32] * lw[lane + 32];
#pragma unroll
  for (int o = 16; o; o >>= 1) p += __shfl_xor_sync(0xffffffffu, p, o);
  if (lane == 0) atomicAdd(&g_gsum[batch[v]], p);
}

__global__ void k_final(const float* __restrict__ lb, float* __restrict__ out, int g) {
  int i = blockIdx.x * blockDim.x + threadIdx.x;
  if (i < g) out[i] = g_gsum[i] / fmaxf(g_gcnt[i], 1.f) + lb[0];
}

// ---------------- launch ----------------------------------------------------------
extern "C" void kernel_launch(void* const* d_in, const int* in_sizes, int n_in,
                              void* d_out, int out_size) {
  int base;
  const int *ei, *bat;
  int Esz;
  if (in_sizes[1] > 1000000) {          // dict order: x, edge_index, batch, ...
    ei = (const int*)d_in[1];
    bat = (const int*)d_in[2];
    base = 3;
    Esz = in_sizes[1];
  } else {                               // signature order
    base = 1;
    ei = (const int*)d_in[15];
    bat = (const int*)d_in[16];
    Esz = in_sizes[15];
  }
  const float* x   = (const float*)d_in[0];
  const float* W1  = (const float*)d_in[base + 0];
  const float* as1 = (const float*)d_in[base + 1];
  const float* ad1 = (const float*)d_in[base + 2];
  const float* b1  = (const float*)d_in[base + 3];
  const float* W2  = (const float*)d_in[base + 4];
  const float* as2 = (const float*)d_in[base + 5];
  const float* ad2 = (const float*)d_in[base + 6];
  const float* b2  = (const float*)d_in[base + 7];
  const float* W3  = (const float*)d_in[base + 8];
  const float* as3 = (const float*)d_in[base + 9];
  const float* ad3 = (const float*)d_in[base + 10];
  const float* b3  = (const float*)d_in[base + 11];
  const float* lw  = (const float*)d_in[base + 12];
  const float* lb  = (const float*)d_in[base + 13];

  int n = in_sizes[0] / 128;
  int E = Esz / 2;
  int G = out_size;

  const int tb = 256;
  int gb = (n + 31) / 32;
  int wg = (n + 7) / 8;
  int E4 = E >> 2;
  int tailE = E - (E4 << 2);
  int nb = (n + SCAN_B - 1) / SCAN_B;

  // CSR build (single stream; scan now parallel 3-phase)
  k_init<<<(n + tb - 1) / tb, tb>>>(n, G);
  k_count<<<(E4 + tailE + tb - 1) / tb, tb>>>(ei, E);
  k_cnt_batch<<<(n + tb - 1) / tb, tb>>>(bat, n);
  k_scan1<<<nb, SCAN_B>>>(n);
  k_scan2<<<1, 128>>>(nb, n);
  k_scan3<<<nb, SCAN_B>>>(n);
  k_scatter<<<(E4 + tailE + n + tb - 1) / tb, tb>>>(ei, E, n);

  k_gemm<<<gb, 128>>>(x, 0, W1, as1, ad1, n, 128);
  k_agg<<<wg, 256>>>(b1, 0, n);
  k_gemm<<<gb, 128>>>(nullptr, 0, W2, as2, ad2, n, 64);
  k_agg<<<wg, 256>>>(b2, 1, n);
  k_gemm<<<gb, 128>>>(nullptr, 1, W3, as3, ad3, n, 64);
  k_agg<<<wg, 256>>>(b3, 0, n);

  k_pool<<<wg, 256>>>(lw, bat, n);
  k_final<<<(G + tb - 1) / tb, tb>>>(lb, (float*)d_out, G);
}

// round 7
// speedup vs baseline: 1.2421x; 1.0357x over previous
#include <cuda_runtime.h>
#include <cuda_fp16.h>

#define NMAX 50000
#define EMAX 800000
#define GMAX 2500
#define ETOT (EMAX + NMAX)
#define SCAN_B 512
#define SCAN_NB ((NMAX + SCAN_B - 1) / SCAN_B)   // 98

// packed dual-fp32 helpers (sm_100+ PTX)
#define PACK2(out, f) asm("mov.b64 %0, {%1, %1};" : "=l"(out) : "r"(__float_as_uint(f)))
#define FMA2(d, a, b) asm("fma.rn.f32x2 %0, %1, %2, %0;" : "+l"(d) : "l"(a), "l"(b))
#define UNPACK2(lo, hi, v) asm("mov.b64 {%0, %1}, %2;" : "=r"(lo), "=r"(hi) : "l"(v))

// ---------------- scratch (device globals; no allocation allowed) ----------------
__device__ uint2 g_h16[NMAX * 32];     // per-layer hidden, fp16: [N][32 lanes x 4 half]
__device__ float g_f0[NMAX * 64];      // layer output ping (fp32)
__device__ float g_f1[NMAX * 64];      // layer output pong
__device__ float g_att[NMAX * 4];      // per node: a_src0, a_src1, a_dst0, a_dst1
__device__ int   g_rp[NMAX + 1];       // CSR row_ptr by dst (pre block-offset)
__device__ int   g_deg[NMAX];
__device__ int   g_fill[NMAX];
__device__ int   g_csrc[ETOT];         // CSR src indices
__device__ float g_gsum[GMAX];
__device__ float g_gcnt[GMAX];
__device__ int   g_bsum[SCAN_NB + 1];
__device__ int   g_boff[SCAN_NB + 1];

// ---------------- CSR build (dst is layer-invariant) + pool zero/count -----------
__global__ void k_init(int n, int g) {
  int i = blockIdx.x * blockDim.x + threadIdx.x;
  if (i < n) { g_deg[i] = 1; g_fill[i] = 0; }   // 1 = self loop
  if (i < g) { g_gsum[i] = 0.f; g_gcnt[i] = 0.f; }
}

// 4 edges/thread deg-count + graph-size count for mean pooling (merged)
__global__ void k_count(const int* __restrict__ ei, const int* __restrict__ batch,
                        int E, int n) {
  int i = blockIdx.x * blockDim.x + threadIdx.x;
  int E4 = E >> 2;
  if (i < E4) {
    int4 d = ((const int4*)(ei + E))[i];
    atomicAdd(&g_deg[d.x], 1);
    atomicAdd(&g_deg[d.y], 1);
    atomicAdd(&g_deg[d.z], 1);
    atomicAdd(&g_deg[d.w], 1);
  } else {
    int j = (E4 << 2) + (i - E4);
    if (j < E) atomicAdd(&g_deg[ei[E + j]], 1);
  }
  if (i < n) atomicAdd(&g_gcnt[batch[i]], 1.f);
}

// ---------- 2-phase exclusive scan of g_deg (block offsets kept separate) --------
__global__ void k_scan1(int n) {
  __shared__ int sh[SCAN_B];
  int t = threadIdx.x;
  int i = blockIdx.x * SCAN_B + t;
  int v = (i < n) ? g_deg[i] : 0;
  sh[t] = v;
  __syncthreads();
#pragma unroll
  for (int o = 1; o < SCAN_B; o <<= 1) {
    int x = (t >= o) ? sh[t - o] : 0;
    __syncthreads();
    sh[t] += x;
    __syncthreads();
  }
  if (i < n) g_rp[i] = sh[t] - v;            // exclusive, pre block-offset
  if (t == SCAN_B - 1) g_bsum[blockIdx.x] = sh[t];
}

__global__ void k_scan2(int nb) {
  __shared__ int sh[128];
  int t = threadIdx.x;
  int v = (t < nb) ? g_bsum[t] : 0;
  sh[t] = v;
  __syncthreads();
#pragma unroll
  for (int o = 1; o < 128; o <<= 1) {
    int x = (t >= o) ? sh[t - o] : 0;
    __syncthreads();
    sh[t] += x;
    __syncthreads();
  }
  if (t < nb) g_boff[t] = sh[t] - v;          // exclusive block offsets
}

// 4 edges per thread; self-loops appended in the same grid.
// final row start = g_rp[d] + g_boff[d>>9].
__global__ void k_scatter(const int* __restrict__ ei, int E, int n) {
  int i = blockIdx.x * blockDim.x + threadIdx.x;
  int E4 = E >> 2;
  if (i < E4) {
    int4 s = ((const int4*)ei)[i];
    int4 d = ((const int4*)(ei + E))[i];
    int px = atomicAdd(&g_fill[d.x], 1);
    int py = atomicAdd(&g_fill[d.y], 1);
    int pz = atomicAdd(&g_fill[d.z], 1);
    int pw = atomicAdd(&g_fill[d.w], 1);
    g_csrc[g_rp[d.x] + g_boff[d.x >> 9] + px] = s.x;
    g_csrc[g_rp[d.y] + g_boff[d.y >> 9] + py] = s.y;
    g_csrc[g_rp[d.z] + g_boff[d.z >> 9] + pz] = s.z;
    g_csrc[g_rp[d.w] + g_boff[d.w >> 9] + pw] = s.w;
  } else {
    int tail = E - (E4 << 2);
    int j = i - E4;
    if (j < tail) {
      int jj = (E4 << 2) + j;
      int s = ei[jj], d = ei[E + jj];
      int pos = atomicAdd(&g_fill[d], 1);
      g_csrc[g_rp[d] + g_boff[d >> 9] + pos] = s;
    } else {
      int v = j - tail;
      if (v < n) {
        int pos = atomicAdd(&g_fill[v], 1);
        g_csrc[g_rp[v] + g_boff[v >> 9] + pos] = v;   // self loop
      }
    }
  }
}

// ---------------- GEMM + fused attention dots -----------------------------------
__global__ void k_gemm(const float* __restrict__ Xin, int insel,
                       const float* __restrict__ W,
                       const float* __restrict__ asrc,
                       const float* __restrict__ adst, int n, int fin) {
  const float* X = Xin ? Xin : (insel ? g_f1 : g_f0);
  __shared__ float xs[32 * 128];
  int tid = threadIdx.x;
  int lane = tid & 31;
  int row0 = blockIdx.x * 32;
  int fin4 = fin >> 2;
  int nf4 = 32 * fin4;
  const float4* X4 = (const float4*)X;
  for (int i = tid; i < nf4; i += 128) {
    int row = i / fin4;
    int kk = i - row * fin4;
    float4 v = make_float4(0.f, 0.f, 0.f, 0.f);
    if (row0 + row < n) v = X4[(row0 + row) * fin4 + kk];
    ((float4*)xs)[i] = v;
  }
  __syncthreads();
  int colg = lane;
  int rowseg = tid >> 5;
  unsigned long long acc[8][2];
#pragma unroll
  for (int r = 0; r < 8; r++) { acc[r][0] = 0ULL; acc[r][1] = 0ULL; }
  const float* xb = &xs[(rowseg * 8) * fin];
  const float* wb = &W[colg * 4];
  for (int k = 0; k < fin; k += 4) {
    ulonglong2 w0 = *(const ulonglong2*)&wb[(k + 0) * 128];
    ulonglong2 w1 = *(const ulonglong2*)&wb[(k + 1) * 128];
    ulonglong2 w2 = *(const ulonglong2*)&wb[(k + 2) * 128];
    ulonglong2 w3 = *(const ulonglong2*)&wb[(k + 3) * 128];
#pragma unroll
    for (int r = 0; r < 8; r++) {
      float4 x4 = *(const float4*)&xb[r * fin + k];
      unsigned long long xx;
      PACK2(xx, x4.x); FMA2(acc[r][0], xx, w0.x); FMA2(acc[r][1], xx, w0.y);
      PACK2(xx, x4.y); FMA2(acc[r][0], xx, w1.x); FMA2(acc[r][1], xx, w1.y);
      PACK2(xx, x4.z); FMA2(acc[r][0], xx, w2.x); FMA2(acc[r][1], xx, w2.y);
      PACK2(xx, x4.w); FMA2(acc[r][0], xx, w3.x); FMA2(acc[r][1], xx, w3.y);
    }
  }
  // epilogue: attention dots (fp32 exact) + fp16 h store
  float4 as4 = *(const float4*)&asrc[colg * 4];
  float4 ad4 = *(const float4*)&adst[colg * 4];
#pragma unroll
  for (int r = 0; r < 8; r++) {
    int row = row0 + rowseg * 8 + r;
    unsigned a, b, c, d;
    UNPACK2(a, b, acc[r][0]);
    UNPACK2(c, d, acc[r][1]);
    float4 hv = make_float4(__uint_as_float(a), __uint_as_float(b),
                            __uint_as_float(c), __uint_as_float(d));
    float ss = hv.x * as4.x + hv.y * as4.y + hv.z * as4.z + hv.w * as4.w;
    float sd = hv.x * ad4.x + hv.y * ad4.y + hv.z * ad4.z + hv.w * ad4.w;
#pragma unroll
    for (int o = 8; o; o >>= 1) {
      ss += __shfl_xor_sync(0xffffffffu, ss, o);
      sd += __shfl_xor_sync(0xffffffffu, sd, o);
    }
    float ss1 = __shfl_sync(0xffffffffu, ss, 16);
    float sd1 = __shfl_sync(0xffffffffu, sd, 16);
    if (row < n) {
      half2 p0 = __floats2half2_rn(hv.x, hv.y);
      half2 p1 = __floats2half2_rn(hv.z, hv.w);
      uint2 hp;
      hp.x = *(unsigned*)&p0;
      hp.y = *(unsigned*)&p1;
      g_h16[row * 32 + colg] = hp;
      if (lane == 0) *(float4*)&g_att[4 * row] = make_float4(ss, ss1, sd, sd1);
    }
  }
}

// ---------------- softmax + aggregate + head-mean + bias + relu ------------------
// lw==nullptr: write node features to OUT. lw!=nullptr (last layer): skip the
// feature store and fuse the global-mean-pool dot product instead.
__global__ void k_agg(const float* __restrict__ bias, int outsel, int n,
                      const float* __restrict__ lw, const int* __restrict__ batch) {
  float* OUT = outsel ? g_f1 : g_f0;
  int v = blockIdx.x * 8 + (threadIdx.x >> 5);
  int lane = threadIdx.x & 31;
  if (v >= n) return;
  int rs = g_rp[v] + g_boff[v >> 9];
  int re = rs + g_deg[v];
  float2 adv = *(const float2*)&g_att[4 * v + 2];
  bool head1 = lane >= 16;

  float s0 = 0.f, s1 = 0.f;
  float4 acc = make_float4(0.f, 0.f, 0.f, 0.f);
  for (int base = rs; base < re; base += 32) {
    int jj = base + lane;
    int s_l = 0;
    float x0 = 0.f, x1 = 0.f;
    if (jj < re) {
      s_l = g_csrc[jj];                                 // coalesced
      float2 as = *(const float2*)&g_att[4 * s_l];      // independent gathers
      float e0 = as.x + adv.x; e0 = fmaxf(e0, 0.2f * e0);
      float e1 = as.y + adv.y; e1 = fmaxf(e1, 0.2f * e1);
      x0 = __expf(e0); x1 = __expf(e1);
    }
    s0 += x0; s1 += x1;
    int cnt = min(re - base, 32);
#pragma unroll 4
    for (int k = 0; k < cnt; k++) {
      int s = __shfl_sync(0xffffffffu, s_l, k);
      float xa = __shfl_sync(0xffffffffu, x0, k);
      float xb = __shfl_sync(0xffffffffu, x1, k);
      float xw = head1 ? xb : xa;
      uint2 hp = g_h16[s * 32 + lane];                  // independent 256B/warp
      float2 f0 = __half22float2(*(half2*)&hp.x);
      float2 f1 = __half22float2(*(half2*)&hp.y);
      acc.x += xw * f0.x; acc.y += xw * f0.y;
      acc.z += xw * f1.x; acc.w += xw * f1.y;
    }
  }
#pragma unroll
  for (int o = 16; o; o >>= 1) {
    s0 += __shfl_xor_sync(0xffffffffu, s0, o);
    s1 += __shfl_xor_sync(0xffffffffu, s1, o);
  }
  float r0 = 0.5f / fmaxf(s0, 1e-16f);
  float r1 = 0.5f / fmaxf(s1, 1e-16f);
  float rw = head1 ? r1 : r0;
  acc.x *= rw; acc.y *= rw; acc.z *= rw; acc.w *= rw;
  float px = __shfl_xor_sync(0xffffffffu, acc.x, 16);
  float py = __shfl_xor_sync(0xffffffffu, acc.y, 16);
  float pz = __shfl_xor_sync(0xffffffffu, acc.z, 16);
  float pw = __shfl_xor_sync(0xffffffffu, acc.w, 16);
  float pdot = 0.f;
  if (!head1) {
    float4 b4 = *(const float4*)&bias[lane * 4];
    float4 o;
    o.x = fmaxf(acc.x + px + b4.x, 0.f);
    o.y = fmaxf(acc.y + py + b4.y, 0.f);
    o.z = fmaxf(acc.z + pz + b4.z, 0.f);
    o.w = fmaxf(acc.w + pw + b4.w, 0.f);
    if (!lw) {
      *(float4*)&OUT[v * 64 + lane * 4] = o;
    } else {
      float4 w4 = *(const float4*)&lw[lane * 4];
      pdot = o.x * w4.x + o.y * w4.y + o.z * w4.z + o.w * w4.w;
    }
  }
  if (lw) {
    // reduce over the 16 low lanes (high lanes contribute 0)
#pragma unroll
    for (int o = 8; o; o >>= 1) pdot += __shfl_xor_sync(0xffffffffu, pdot, o);
    if (lane == 0) atomicAdd(&g_gsum[batch[v]], pdot);
  }
}

// ---------------- final linear -----------------------------------------
__global__ void k_final(const float* __restrict__ lb, float* __restrict__ out, int g) {
  int i = blockIdx.x * blockDim.x + threadIdx.x;
  if (i < g) out[i] = g_gsum[i] / fmaxf(g_gcnt[i], 1.f) + lb[0];
}

// ---------------- launch ----------------------------------------------------------
extern "C" void kernel_launch(void* const* d_in, const int* in_sizes, int n_in,
                              void* d_out, int out_size) {
  int base;
  const int *ei, *bat;
  int Esz;
  if (in_sizes[1] > 1000000) {          // dict order: x, edge_index, batch, ...
    ei = (const int*)d_in[1];
    bat = (const int*)d_in[2];
    base = 3;
    Esz = in_sizes[1];
  } else {                               // signature order
    base = 1;
    ei = (const int*)d_in[15];
    bat = (const int*)d_in[16];
    Esz = in_sizes[15];
  }
  const float* x   = (const float*)d_in[0];
  const float* W1  = (const float*)d_in[base + 0];
  const float* as1 = (const float*)d_in[base + 1];
  const float* ad1 = (const float*)d_in[base + 2];
  const float* b1  = (const float*)d_in[base + 3];
  const float* W2  = (const float*)d_in[base + 4];
  const float* as2 = (const float*)d_in[base + 5];
  const float* ad2 = (const float*)d_in[base + 6];
  const float* b2  = (const float*)d_in[base + 7];
  const float* W3  = (const float*)d_in[base + 8];
  const float* as3 = (const float*)d_in[base + 9];
  const float* ad3 = (const float*)d_in[base + 10];
  const float* b3  = (const float*)d_in[base + 11];
  const float* lw  = (const float*)d_in[base + 12];
  const float* lb  = (const float*)d_in[base + 13];

  int n = in_sizes[0] / 128;
  int E = Esz / 2;
  int G = out_size;

  const int tb = 256;
  int gb = (n + 31) / 32;
  int wg = (n + 7) / 8;
  int E4 = E >> 2;
  int tailE = E - (E4 << 2);
  int nb = (n + SCAN_B - 1) / SCAN_B;
  int cntGrid = ((E4 + tailE > n ? E4 + tailE : n) + tb - 1) / tb;

  // CSR build
  k_init<<<(n + tb - 1) / tb, tb>>>(n, G);
  k_count<<<cntGrid, tb>>>(ei, bat, E, n);
  k_scan1<<<nb, SCAN_B>>>(n);
  k_scan2<<<1, 128>>>(nb);
  k_scatter<<<(E4 + tailE + n + tb - 1) / tb, tb>>>(ei, E, n);

  k_gemm<<<gb, 128>>>(x, 0, W1, as1, ad1, n, 128);
  k_agg<<<wg, 256>>>(b1, 0, n, nullptr, nullptr);
  k_gemm<<<gb, 128>>>(nullptr, 0, W2, as2, ad2, n, 64);
  k_agg<<<wg, 256>>>(b2, 1, n, nullptr, nullptr);
  k_gemm<<<gb, 128>>>(nullptr, 1, W3, as3, ad3, n, 64);
  k_agg<<<wg, 256>>>(b3, 0, n, lw, bat);        // fused global-mean-pool dot

  k_final<<<(G + tb - 1) / tb, tb>>>(lb, (float*)d_out, G);
}